// round 3
// baseline (speedup 1.0000x reference)
#include <cuda_runtime.h>
#include <math.h>

#define NB 4
#define NT 1024
#define NCH 4
#define NF 481
#define NK 48
#define NPV 16
#define DT_MS 10.0f
#define MAIN_THREADS 192

// ---------- device scratch (static, no allocation) ----------
__device__ float4 g_band4[(NF * NK) / 2];          // per f: 48 complex (re,im) = 24 float4
__device__ float  g_dsinv[NK];                     // 1 / max(sum_f band_real, 1e-20)
__device__ float  g_pvx[NB * NT * NK * NPV];       // pre-IIR power vectors (B,T,K,P), 12.6 MB

// ---------- f32x2 packed-FMA helpers ----------
__device__ __forceinline__ void fma2(unsigned long long& c, unsigned long long a, unsigned long long b) {
    asm("fma.rn.f32x2 %0, %1, %2, %0;" : "+l"(c) : "l"(a), "l"(b));
}
__device__ __forceinline__ float2 upk2(unsigned long long v) {
    float2 r;
    asm("mov.b64 {%0, %1}, %2;" : "=f"(r.x), "=f"(r.y) : "l"(v));
    return r;
}

// ---------- prep: interleave band into (re,im) pairs ----------
__global__ void prep_band_kernel(const float* __restrict__ br, const float* __restrict__ bi) {
    int i = blockIdx.x * blockDim.x + threadIdx.x;
    if (i < NF * NK) {
        ((float2*)g_band4)[i] = make_float2(br[i], bi[i]);
    }
}

// ---------- prep: dsinv[k] = 1 / max(sum_f band_real, 1e-20) ----------
__global__ void prep_ds_kernel(const float* __restrict__ br) {
    __shared__ float red[64];
    int k = blockIdx.x, tx = threadIdx.x;
    float s = 0.f;
    for (int f = tx; f < NF; f += 64) s += br[f * NK + k];
    red[tx] = s;
    __syncthreads();
    for (int off = 32; off > 0; off >>= 1) {
        if (tx < off) red[tx] += red[tx + off];
        __syncthreads();
    }
    if (tx == 0) g_dsinv[k] = 1.0f / fmaxf(red[0], 1e-20f);
}

// ---------- main: one block per (b,t) ----------
// smem (floats):
//   sD   [0,        4*NF)  : diag streams d0..d3, scalar, stride NF
//   sP   [4*NF,    16*NF)  : 6 pair streams (ur,ui) as float2, stride NF
//   sA2  [16*NF,   48*NF)  : 16 multiplier streams as duplicated float2 (a,a)
//   sM   [48*NF, 48*NF+512): real 16x32 projection
//   after pass 3, sD/sP region reused: sAcc float2[48*16], then sBC float[48*32]
__global__ __launch_bounds__(MAIN_THREADS, 2)
void pv_main_kernel(const float* __restrict__ bins_real,
                    const float* __restrict__ bins_imag,
                    const float* __restrict__ c2pv_real,
                    const float* __restrict__ c2pv_imag) {
    extern __shared__ float smem[];
    float*  sD  = smem;
    float2* sP  = (float2*)(smem + 4 * NF);
    float2* sA2 = (float2*)(smem + 16 * NF);
    float*  sM  = smem + 48 * NF;
    float2* sAcc = (float2*)smem;
    float*  sBC  = smem + 1536;

    const int tid = threadIdx.x;
    const int bt  = blockIdx.x;
    const int b   = bt >> 10;
    const int t   = bt & (NT - 1);

    // projection matrix: pv[p] = sum_c Re(c2pv)*bc_re - Im(c2pv)*bc_im
    for (int i = tid; i < NPV * 32; i += MAIN_THREADS) {
        int p = i >> 5, r = i & 31, c = r >> 1;
        sM[i] = (r & 1) ? -c2pv_imag[p * 16 + c] : c2pv_real[p * 16 + c];
    }

    // ---- pass 1: trace-normalized covariance ----
    const long base = ((long)(b * NT + t)) * NCH * NF;
    for (int f = tid; f < NF; f += MAIN_THREADS) {
        float xr[NCH], xi[NCH];
        #pragma unroll
        for (int ch = 0; ch < NCH; ch++) {
            xr[ch] = bins_real[base + ch * NF + f];
            xi[ch] = bins_imag[base + ch * NF + f];
        }
        float d[NCH];
        float pw = 0.f;
        #pragma unroll
        for (int i = 0; i < NCH; i++) {
            d[i] = xr[i] * xr[i] + xi[i] * xi[i];
            pw += d[i];
        }
        float inv = 1.0f / fmaxf(pw, 1e-20f);
        #pragma unroll
        for (int i = 0; i < NCH; i++) sD[i * NF + f] = d[i] * inv;
        int m = 0;
        #pragma unroll
        for (int i = 0; i < NCH; i++) {
            #pragma unroll
            for (int j = i + 1; j < NCH; j++) {
                float ur = xr[i] * xr[j] + xi[i] * xi[j];
                float ui = xi[i] * xr[j] - xr[i] * xi[j];
                sP[m * NF + f] = make_float2(ur * inv, ui * inv);
                m++;
            }
        }
    }
    __syncthreads();

    // ---- pass 2: phase adjust  adj = z * (nu * rsqrt(nu*nz)),  z = conj(c_lo)*c_hi ----
    for (int f = tid; f < NF; f += MAIN_THREADS) {
        int lo = f - 1;
        if (lo < 0) lo = 0;
        if (lo > NF - 3) lo = NF - 3;
        int hi = lo + 2;
        #pragma unroll
        for (int i = 0; i < 4; i++) {
            float d = sD[i * NF + f];
            sA2[i * NF + f] = make_float2(d, d);
        }
        #pragma unroll
        for (int m = 0; m < 6; m++) {
            float2 u = sP[m * NF + f];
            float2 L = sP[m * NF + lo];
            float2 H = sP[m * NF + hi];
            float zr = L.x * H.x + L.y * H.y;
            float zi = L.x * H.y - L.y * H.x;
            float nu = u.x * u.x + u.y * u.y;
            float nz = zr * zr + zi * zi;
            float s = nu * rsqrtf(fmaxf(nu * nz, 1e-37f));
            float ar = zr * s;
            float ai = zi * s;
            sA2[(4 + m) * NF + f]  = make_float2(ar, ar);
            sA2[(10 + m) * NF + f] = make_float2(ai, ai);
        }
    }
    __syncthreads();

    // ---- pass 3: acc[k,stream] += a[stream,f] * band[f,k]  (f32x2, zero-MOV body) ----
    const int cp = tid & 15;   // stream: 0..3 diag, 4..9 P(Re), 10..15 Q(Im)
    const int kg = tid >> 4;   // 0..11, 4 consecutive k each
    unsigned long long A0 = 0, A1 = 0, A2 = 0, A3 = 0;
    const unsigned long long* aptr = (const unsigned long long*)(sA2 + cp * NF);
    const ulonglong2* bptr = (const ulonglong2*)g_band4 + kg * 2;
    #pragma unroll 8
    for (int f = 0; f < NF; f++) {
        unsigned long long Av = aptr[f];
        ulonglong2 b0 = bptr[f * 24];
        ulonglong2 b1 = bptr[f * 24 + 1];
        fma2(A0, Av, b0.x);
        fma2(A1, Av, b0.y);
        fma2(A2, Av, b1.x);
        fma2(A3, Av, b1.y);
    }
    __syncthreads();   // all reads of sA2 done before sAcc overwrites sD/sP region? (sAcc is in sD/sP, safe) — barrier orders pass-3 reads before pass-4 consumers
    {
        int k0 = kg * 4;
        sAcc[(k0 + 0) * 16 + cp] = upk2(A0);
        sAcc[(k0 + 1) * 16 + cp] = upk2(A1);
        sAcc[(k0 + 2) * 16 + cp] = upk2(A2);
        sAcc[(k0 + 3) * 16 + cp] = upk2(A3);
    }
    __syncthreads();

    // ---- pass 4: reconstruct Hermitian bc[k][16 complex] ----
    if (tid < NK) {
        const int pi[6] = {0, 0, 0, 1, 1, 2};
        const int pj[6] = {1, 2, 3, 2, 3, 3};
        const float2* row = sAcc + tid * 16;
        float* bc = sBC + tid * 32;
        #pragma unroll
        for (int i = 0; i < 4; i++) {
            float2 D = row[i];
            bc[(i * 4 + i) * 2]     = D.x;
            bc[(i * 4 + i) * 2 + 1] = D.y;
        }
        #pragma unroll
        for (int m = 0; m < 6; m++) {
            float2 Pm = row[4 + m];
            float2 Qm = row[10 + m];
            int cij = pi[m] * 4 + pj[m];
            int cji = pj[m] * 4 + pi[m];
            bc[cij * 2]     = Pm.x - Qm.y;
            bc[cij * 2 + 1] = Pm.y + Qm.x;
            bc[cji * 2]     = Pm.x + Qm.y;
            bc[cji * 2 + 1] = Pm.y - Qm.x;
        }
    }
    __syncthreads();

    // ---- pass 5: pvx[k,p] = Re(c2pv . bc) * dsinv[k] ----
    float* outBase = g_pvx + ((long)(b * NT + t)) * NK * NPV;
    for (int idx = tid; idx < NK * NPV; idx += MAIN_THREADS) {
        int k = idx >> 4, p = idx & 15;
        const float* mrow = sM + p * 32;
        const float* brow = sBC + k * 32;
        float s = 0.f;
        #pragma unroll
        for (int r = 0; r < 32; r++) s = fmaf(mrow[r], brow[r], s);
        outBase[idx] = s * g_dsinv[k];
    }
}

// ---------- IIR: one block per (b,k); chunked scan in smem ----------
// smem: sX[64][16][16]  (sX[t%64][t/64][p]) = 16384 floats, + sE[16*17] + sC[16*17]
__global__ __launch_bounds__(256)
void iir_kernel(const float* __restrict__ tau, float* __restrict__ out) {
    extern __shared__ float sm[];
    float* sX = sm;
    float* sE = sm + 16384;
    float* sC = sE + 16 * 17;

    const int tid = threadIdx.x;
    const int k = blockIdx.x % NK;
    const int b = blockIdx.x / NK;

    const float alpha = __expf(-DT_MS / tau[k]);
    const float beta = 1.0f - alpha;
    float a64 = alpha * alpha;     // ^2
    a64 = a64 * a64;               // ^4
    a64 = a64 * a64;               // ^8
    a64 = a64 * a64;               // ^16
    a64 = a64 * a64;               // ^32
    a64 = a64 * a64;               // ^64

    // load 64KB slab (B,T,K,P) -> sX[t%64][t/64][p], float4 coalesced
    const float4* src = (const float4*)(g_pvx + ((long)b * NT * NK + k) * NPV);
    #pragma unroll 4
    for (int i4 = tid; i4 < NT * NPV / 4; i4 += 256) {
        int t = i4 >> 2;           // 4 float4 per t? no: 16 floats per t = 4 float4
        int p4 = (i4 & 3) * 4;
        float4 v = src[t * (NK * NPV / 4) + (i4 & 3)];
        *(float4*)&sX[(t & 63) * 256 + (t >> 6) * 16 + p4] = v;
    }
    __syncthreads();

    const int p = tid & 15;
    const int c = tid >> 4;        // chunk 0..15, 64 steps each

    // pass A: local IIR (zero init; chunk 0 uses the y0=x0 rule), record chunk end
    {
        float y;
        int i0;
        if (c == 0) { y = sX[p]; i0 = 1; }
        else        { y = 0.0f;  i0 = 0; }
        for (int i = i0; i < 64; i++) {
            float x = sX[i * 256 + c * 16 + p];
            y = fmaf(alpha, y, beta * x);
        }
        sE[p * 17 + c] = y;
    }
    __syncthreads();

    // pass B: serial carry scan per p (16 threads)
    if (tid < 16) {
        int pp = tid;
        float cur = sE[pp * 17 + 0];       // actual end of chunk 0
        sC[pp * 17 + 1] = cur;
        #pragma unroll
        for (int cc = 2; cc < 16; cc++) {
            cur = fmaf(a64, cur, sE[pp * 17 + cc - 1]);
            sC[pp * 17 + cc] = cur;
        }
    }
    __syncthreads();

    // pass C: exact re-run with corrected init, write in place
    {
        float y;
        int i0;
        if (c == 0) {
            y = sX[p];
            i0 = 1;                       // sX[0][0][p] already equals y_0 = x_0
        } else {
            y = sC[p * 17 + c];
            i0 = 0;
        }
        for (int i = i0; i < 64; i++) {
            int a = i * 256 + c * 16 + p;
            float x = sX[a];
            y = fmaf(alpha, y, beta * x);
            sX[a] = y;
        }
    }
    __syncthreads();

    // store to (B,K,T,P), float4 coalesced
    float4* dst = (float4*)(out + ((long)(b * NK + k)) * NT * NPV);
    #pragma unroll 4
    for (int i4 = tid; i4 < NT * NPV / 4; i4 += 256) {
        int t = i4 >> 2;
        int p4 = (i4 & 3) * 4;
        dst[i4] = *(float4*)&sX[(t & 63) * 256 + (t >> 6) * 16 + p4];
    }
}

extern "C" void kernel_launch(void* const* d_in, const int* in_sizes, int n_in,
                              void* d_out, int out_size) {
    const float* bins_real = (const float*)d_in[0];
    const float* bins_imag = (const float*)d_in[1];
    const float* band_real = (const float*)d_in[2];
    const float* band_imag = (const float*)d_in[3];
    const float* c2pv_real = (const float*)d_in[4];
    const float* c2pv_imag = (const float*)d_in[5];
    const float* tau       = (const float*)d_in[6];
    float* out = (float*)d_out;

    const int main_smem = (48 * NF + 512) * (int)sizeof(float);        // 94,400 B
    const int iir_smem  = (16384 + 2 * 16 * 17) * (int)sizeof(float);  // 67,712 B
    cudaFuncSetAttribute((const void*)pv_main_kernel,
                         cudaFuncAttributeMaxDynamicSharedMemorySize, main_smem);
    cudaFuncSetAttribute((const void*)iir_kernel,
                         cudaFuncAttributeMaxDynamicSharedMemorySize, iir_smem);

    prep_band_kernel<<<(NF * NK + 255) / 256, 256>>>(band_real, band_imag);
    prep_ds_kernel<<<NK, 64>>>(band_real);
    pv_main_kernel<<<NB * NT, MAIN_THREADS, main_smem>>>(bins_real, bins_imag,
                                                         c2pv_real, c2pv_imag);
    iir_kernel<<<NB * NK, 256, iir_smem>>>(tau, out);
}

// round 4
// speedup vs baseline: 1.1838x; 1.1838x over previous
#include <cuda_runtime.h>
#include <math.h>

#define NB 4
#define NT 1024
#define NCH 4
#define NF 481
#define NK 48
#define NPV 16
#define DT_MS 10.0f
#define MAIN_THREADS 192

// ---------- device scratch (static, no allocation) ----------
__device__ float4 g_band4[(NF * NK) / 2];          // per f: 48 complex (re,im) = 24 float4
__device__ float  g_dsinv[NK];                     // 1 / max(sum_f band_real, 1e-20)
__device__ float  g_pvx[NB * NT * NK * NPV];       // pre-IIR power vectors (B,T,K,P), 12.6 MB

// ---------- f32x2 packed-FMA helpers ----------
__device__ __forceinline__ unsigned long long pk2(float x, float y) {
    unsigned long long r;
    asm("mov.b64 %0, {%1, %2};" : "=l"(r) : "f"(x), "f"(y));
    return r;
}
__device__ __forceinline__ void fma2(unsigned long long& c, unsigned long long a, unsigned long long b) {
    asm("fma.rn.f32x2 %0, %1, %2, %0;" : "+l"(c) : "l"(a), "l"(b));
}
__device__ __forceinline__ float2 upk2(unsigned long long v) {
    float2 r;
    asm("mov.b64 {%0, %1}, %2;" : "=f"(r.x), "=f"(r.y) : "l"(v));
    return r;
}

// ---------- prep: interleave band into (re,im) pairs ----------
__global__ void prep_band_kernel(const float* __restrict__ br, const float* __restrict__ bi) {
    int i = blockIdx.x * blockDim.x + threadIdx.x;
    if (i < NF * NK) {
        ((float2*)g_band4)[i] = make_float2(br[i], bi[i]);
    }
}

// ---------- prep: dsinv[k] = 1 / max(sum_f band_real, 1e-20) ----------
__global__ void prep_ds_kernel(const float* __restrict__ br) {
    __shared__ float red[64];
    int k = blockIdx.x, tx = threadIdx.x;
    float s = 0.f;
    for (int f = tx; f < NF; f += 64) s += br[f * NK + k];
    red[tx] = s;
    __syncthreads();
    for (int off = 32; off > 0; off >>= 1) {
        if (tx < off) red[tx] += red[tx + off];
        __syncthreads();
    }
    if (tx == 0) g_dsinv[k] = 1.0f / fmaxf(red[0], 1e-20f);
}

// ---------- main: one block per (b,t) ----------
// smem (floats), total 63,616 B -> 3 blocks/SM:
//   sCov [0,      16*NF) : {d0..d3, (ur,ui) x 6}[f], component-major, stride NF
//   sA   [16*NF,  32*NF) : multiplier streams {d0..d3, ar0..5, ai0..5}[f], scalar
//   sM   [32*NF, +512)   : real 16x32 projection
//   after pass 3, sCov region reused: sAcc float2[48*16] at 0, sBC float[48*32] at 2048
__global__ __launch_bounds__(MAIN_THREADS, 3)
void pv_main_kernel(const float* __restrict__ bins_real,
                    const float* __restrict__ bins_imag,
                    const float* __restrict__ c2pv_real,
                    const float* __restrict__ c2pv_imag) {
    extern __shared__ float smem[];
    float*  sCov = smem;
    float*  sA   = smem + 16 * NF;
    float*  sM   = smem + 32 * NF;
    float2* sAcc = (float2*)smem;
    float*  sBC  = smem + 2048;

    const int tid = threadIdx.x;
    const int bt  = blockIdx.x;
    const int b   = bt >> 10;
    const int t   = bt & (NT - 1);

    // projection matrix: pv[p] = sum_c Re(c2pv)*bc_re - Im(c2pv)*bc_im
    for (int i = tid; i < NPV * 32; i += MAIN_THREADS) {
        int p = i >> 5, r = i & 31, c = r >> 1;
        sM[i] = (r & 1) ? -c2pv_imag[p * 16 + c] : c2pv_real[p * 16 + c];
    }

    // ---- pass 1: trace-normalized covariance ----
    const long base = ((long)(b * NT + t)) * NCH * NF;
    for (int f = tid; f < NF; f += MAIN_THREADS) {
        float xr[NCH], xi[NCH];
        #pragma unroll
        for (int ch = 0; ch < NCH; ch++) {
            xr[ch] = bins_real[base + ch * NF + f];
            xi[ch] = bins_imag[base + ch * NF + f];
        }
        float d[NCH];
        float pw = 0.f;
        #pragma unroll
        for (int i = 0; i < NCH; i++) {
            d[i] = xr[i] * xr[i] + xi[i] * xi[i];
            pw += d[i];
        }
        float inv = 1.0f / fmaxf(pw, 1e-20f);
        #pragma unroll
        for (int i = 0; i < NCH; i++) sCov[i * NF + f] = d[i] * inv;
        int m = 0;
        #pragma unroll
        for (int i = 0; i < NCH; i++) {
            #pragma unroll
            for (int j = i + 1; j < NCH; j++) {
                float ur = xr[i] * xr[j] + xi[i] * xi[j];
                float ui = xi[i] * xr[j] - xr[i] * xi[j];
                sCov[(4 + 2 * m) * NF + f] = ur * inv;
                sCov[(5 + 2 * m) * NF + f] = ui * inv;
                m++;
            }
        }
    }
    __syncthreads();

    // ---- pass 2: phase adjust  adj = z * (nu * rsqrt(nu*nz)),  z = conj(c_lo)*c_hi ----
    for (int f = tid; f < NF; f += MAIN_THREADS) {
        int lo = f - 1;
        if (lo < 0) lo = 0;
        if (lo > NF - 3) lo = NF - 3;
        int hi = lo + 2;
        #pragma unroll
        for (int i = 0; i < 4; i++) sA[i * NF + f] = sCov[i * NF + f];
        #pragma unroll
        for (int m = 0; m < 6; m++) {
            float ur = sCov[(4 + 2 * m) * NF + f];
            float uv = sCov[(5 + 2 * m) * NF + f];
            float lr = sCov[(4 + 2 * m) * NF + lo];
            float li = sCov[(5 + 2 * m) * NF + lo];
            float hr = sCov[(4 + 2 * m) * NF + hi];
            float hv = sCov[(5 + 2 * m) * NF + hi];
            float zr = lr * hr + li * hv;
            float zi = lr * hv - li * hr;
            float nu = ur * ur + uv * uv;
            float nz = zr * zr + zi * zi;
            float s = nu * rsqrtf(fmaxf(nu * nz, 1e-37f));
            sA[(4 + m) * NF + f]  = zr * s;
            sA[(10 + m) * NF + f] = zi * s;
        }
    }
    __syncthreads();

    // ---- pass 3: acc[k,stream] += a[stream,f] * band[f,k]  (f32x2, deep unroll) ----
    const int cp = tid & 15;   // stream: 0..3 diag, 4..9 P(Re), 10..15 Q(Im)
    const int kg = tid >> 4;   // 0..11, 4 consecutive k each
    unsigned long long A0 = 0, A1 = 0, A2 = 0, A3 = 0;
    const float* aptr = sA + cp * NF;
    const ulonglong2* bptr = (const ulonglong2*)g_band4 + kg * 2;
    int f = 0;
    for (; f + 8 <= NF; f += 8) {
        #pragma unroll
        for (int u = 0; u < 8; u++) {
            float a = aptr[f + u];
            ulonglong2 b0 = bptr[(f + u) * 24];
            ulonglong2 b1 = bptr[(f + u) * 24 + 1];
            unsigned long long Av = pk2(a, a);
            fma2(A0, Av, b0.x);
            fma2(A1, Av, b0.y);
            fma2(A2, Av, b1.x);
            fma2(A3, Av, b1.y);
        }
    }
    for (; f < NF; f++) {
        float a = aptr[f];
        ulonglong2 b0 = bptr[f * 24];
        ulonglong2 b1 = bptr[f * 24 + 1];
        unsigned long long Av = pk2(a, a);
        fma2(A0, Av, b0.x);
        fma2(A1, Av, b0.y);
        fma2(A2, Av, b1.x);
        fma2(A3, Av, b1.y);
    }
    __syncthreads();   // all pass-3 reads of sA/sCov done before sAcc overwrites
    {
        int k0 = kg * 4;
        sAcc[(k0 + 0) * 16 + cp] = upk2(A0);
        sAcc[(k0 + 1) * 16 + cp] = upk2(A1);
        sAcc[(k0 + 2) * 16 + cp] = upk2(A2);
        sAcc[(k0 + 3) * 16 + cp] = upk2(A3);
    }
    __syncthreads();

    // ---- pass 4: reconstruct Hermitian bc[k][16 complex] ----
    if (tid < NK) {
        const int pi[6] = {0, 0, 0, 1, 1, 2};
        const int pj[6] = {1, 2, 3, 2, 3, 3};
        const float2* row = sAcc + tid * 16;
        float* bc = sBC + tid * 32;
        #pragma unroll
        for (int i = 0; i < 4; i++) {
            float2 D = row[i];
            bc[(i * 4 + i) * 2]     = D.x;
            bc[(i * 4 + i) * 2 + 1] = D.y;
        }
        #pragma unroll
        for (int m = 0; m < 6; m++) {
            float2 Pm = row[4 + m];
            float2 Qm = row[10 + m];
            int cij = pi[m] * 4 + pj[m];
            int cji = pj[m] * 4 + pi[m];
            bc[cij * 2]     = Pm.x - Qm.y;
            bc[cij * 2 + 1] = Pm.y + Qm.x;
            bc[cji * 2]     = Pm.x + Qm.y;
            bc[cji * 2 + 1] = Pm.y - Qm.x;
        }
    }
    __syncthreads();

    // ---- pass 5: pvx[k,p] = Re(c2pv . bc) * dsinv[k] ----
    float* outBase = g_pvx + ((long)(b * NT + t)) * NK * NPV;
    for (int idx = tid; idx < NK * NPV; idx += MAIN_THREADS) {
        int k = idx >> 4, p = idx & 15;
        const float* mrow = sM + p * 32;
        const float* brow = sBC + k * 32;
        float s = 0.f;
        #pragma unroll
        for (int r = 0; r < 32; r++) s = fmaf(mrow[r], brow[r], s);
        outBase[idx] = s * g_dsinv[k];
    }
}

// ---------- IIR: one block per (b,k); chunked scan in smem ----------
__global__ __launch_bounds__(256)
void iir_kernel(const float* __restrict__ tau, float* __restrict__ out) {
    extern __shared__ float sm[];
    float* sX = sm;
    float* sE = sm + 16384;
    float* sC = sE + 16 * 17;

    const int tid = threadIdx.x;
    const int k = blockIdx.x % NK;
    const int b = blockIdx.x / NK;

    const float alpha = __expf(-DT_MS / tau[k]);
    const float beta = 1.0f - alpha;
    float a64 = alpha * alpha;
    a64 = a64 * a64;
    a64 = a64 * a64;
    a64 = a64 * a64;
    a64 = a64 * a64;
    a64 = a64 * a64;   // alpha^64

    const float4* src = (const float4*)(g_pvx + ((long)b * NT * NK + k) * NPV);
    #pragma unroll 4
    for (int i4 = tid; i4 < NT * NPV / 4; i4 += 256) {
        int t = i4 >> 2;
        int p4 = (i4 & 3) * 4;
        float4 v = src[t * (NK * NPV / 4) + (i4 & 3)];
        *(float4*)&sX[(t & 63) * 256 + (t >> 6) * 16 + p4] = v;
    }
    __syncthreads();

    const int p = tid & 15;
    const int c = tid >> 4;

    // pass A: local IIR from zero init (chunk 0: real init y0=x0)
    {
        float y;
        int i0;
        if (c == 0) { y = sX[p]; i0 = 1; }
        else        { y = 0.0f;  i0 = 0; }
        for (int i = i0; i < 64; i++) {
            float x = sX[i * 256 + c * 16 + p];
            y = fmaf(alpha, y, beta * x);
        }
        sE[p * 17 + c] = y;
    }
    __syncthreads();

    // pass B: serial carry scan per p
    if (tid < 16) {
        int pp = tid;
        float cur = sE[pp * 17 + 0];
        sC[pp * 17 + 1] = cur;
        #pragma unroll
        for (int cc = 2; cc < 16; cc++) {
            cur = fmaf(a64, cur, sE[pp * 17 + cc - 1]);
            sC[pp * 17 + cc] = cur;
        }
    }
    __syncthreads();

    // pass C: re-run with corrected init, write in place
    {
        float y;
        int i0;
        if (c == 0) { y = sX[p]; i0 = 1; }
        else        { y = sC[p * 17 + c]; i0 = 0; }
        for (int i = i0; i < 64; i++) {
            int a = i * 256 + c * 16 + p;
            float x = sX[a];
            y = fmaf(alpha, y, beta * x);
            sX[a] = y;
        }
    }
    __syncthreads();

    float4* dst = (float4*)(out + ((long)(b * NK + k)) * NT * NPV);
    #pragma unroll 4
    for (int i4 = tid; i4 < NT * NPV / 4; i4 += 256) {
        int t = i4 >> 2;
        int p4 = (i4 & 3) * 4;
        dst[i4] = *(float4*)&sX[(t & 63) * 256 + (t >> 6) * 16 + p4];
    }
}

extern "C" void kernel_launch(void* const* d_in, const int* in_sizes, int n_in,
                              void* d_out, int out_size) {
    const float* bins_real = (const float*)d_in[0];
    const float* bins_imag = (const float*)d_in[1];
    const float* band_real = (const float*)d_in[2];
    const float* band_imag = (const float*)d_in[3];
    const float* c2pv_real = (const float*)d_in[4];
    const float* c2pv_imag = (const float*)d_in[5];
    const float* tau       = (const float*)d_in[6];
    float* out = (float*)d_out;

    const int main_smem = (32 * NF + 512) * (int)sizeof(float);        // 63,616 B -> 3 blocks/SM
    const int iir_smem  = (16384 + 2 * 16 * 17) * (int)sizeof(float);  // 67,712 B
    cudaFuncSetAttribute((const void*)pv_main_kernel,
                         cudaFuncAttributeMaxDynamicSharedMemorySize, main_smem);
    cudaFuncSetAttribute((const void*)iir_kernel,
                         cudaFuncAttributeMaxDynamicSharedMemorySize, iir_smem);

    prep_band_kernel<<<(NF * NK + 255) / 256, 256>>>(band_real, band_imag);
    prep_ds_kernel<<<NK, 64>>>(band_real);
    pv_main_kernel<<<NB * NT, MAIN_THREADS, main_smem>>>(bins_real, bins_imag,
                                                         c2pv_real, c2pv_imag);
    iir_kernel<<<NB * NK, 256, iir_smem>>>(tau, out);
}